// round 8
// baseline (speedup 1.0000x reference)
#include <cuda_runtime.h>

// Projection: per row i of x[N,128]:
//   sq = sum(x_i^2); s = (sq-1)/(sq+1); out_i = [(1-s)*x_i, s]  -> out[N,129]
// with (1-s) = 2/(1+sq).
//
// Converged HBM-bound config. Evidence across rounds:
//  R1: 516B-stride stores merge fully in L2 (DRAM traffic == payload).
//  R2: smem staging for aligned stores costs +18us, zero traffic benefit.
//  R3: scalar stride-32 __ldcs loads, 4 rows/warp -> best DRAM% (84.2).
//  R4: doubling MLP again: neutral (supply-side not the limiter).
//  R5: float4 loads: neutral-to-slightly-worse DRAM% (81.9).
// => mixed r/w HBM wall ~6.7TB/s. This round: R3 memory pattern + R5's
// de-predicated tail store (lanes 0-3 store the 4 row tails in one STG).

#define D 128
#define THREADS 256
#define WARPS (THREADS / 32)
#define ROWS_PER_WARP 4
#define ROWS_PER_BLOCK (WARPS * ROWS_PER_WARP)   // 32

__global__ void __launch_bounds__(THREADS) projection_kernel(
    const float* __restrict__ x, float* __restrict__ out)
{
    const int warp = threadIdx.x >> 5;
    const int lane = threadIdx.x & 31;
    const long long row0 = (long long)blockIdx.x * ROWS_PER_BLOCK
                         + (long long)warp * ROWS_PER_WARP;

    const float* __restrict__ xr = x + row0 * D + lane;

    // Front-batched, fully coalesced streaming loads: 16 x LDG.32.CS
    float v[ROWS_PER_WARP][4];
    #pragma unroll
    for (int r = 0; r < ROWS_PER_WARP; r++)
        #pragma unroll
        for (int c = 0; c < 4; c++)
            v[r][c] = __ldcs(xr + r * D + c * 32);

    float sq[ROWS_PER_WARP];
    #pragma unroll
    for (int r = 0; r < ROWS_PER_WARP; r++)
        sq[r] = v[r][0] * v[r][0] + v[r][1] * v[r][1]
              + v[r][2] * v[r][2] + v[r][3] * v[r][3];

    // Interleaved warp reductions; afterwards every lane holds all sq[r]
    #pragma unroll
    for (int off = 16; off > 0; off >>= 1)
        #pragma unroll
        for (int r = 0; r < ROWS_PER_WARP; r++)
            sq[r] += __shfl_xor_sync(0xFFFFFFFFu, sq[r], off);

    #pragma unroll
    for (int r = 0; r < ROWS_PER_WARP; r++) {
        const float inv   = 1.0f / (1.0f + sq[r]);
        const float scale = 2.0f * inv;        // = 1 - s

        float* __restrict__ orow = out + (row0 + r) * (D + 1);
        #pragma unroll
        for (int c = 0; c < 4; c++)
            orow[lane + c * 32] = scale * v[r][c];
    }

    // Tail scalars: lane r stores s for row (row0 + r) — one STG, 4 active lanes.
    if (lane < ROWS_PER_WARP) {
        const float sql = sq[lane];
        out[(row0 + lane) * (D + 1) + D] = (sql - 1.0f) / (1.0f + sql);
    }
}

extern "C" void kernel_launch(void* const* d_in, const int* in_sizes, int n_in,
                              void* d_out, int out_size)
{
    const float* x = (const float*)d_in[0];
    float* out = (float*)d_out;
    const int n_rows = in_sizes[0] / D;                    // 1048576
    const int blocks = n_rows / ROWS_PER_BLOCK;            // exact: 32768
    projection_kernel<<<blocks, THREADS>>>(x, out);
}

// round 9
// speedup vs baseline: 1.0281x; 1.0281x over previous
#include <cuda_runtime.h>

// Projection: per row i of x[N,128]:
//   sq = sum(x_i^2); s = (sq-1)/(sq+1); out_i = [(1-s)*x_i, s]  -> out[N,129]
// with (1-s) = 2/(1+sq).
//
// Converged HBM-bound config (R3-R8 all ~153-157us ncu, DRAM 82-84%).
// R9 A/B: __stcs streaming stores (evict-first) — the one cache-policy knob
// not yet measured. Helps if it frees L2 ways for the misaligned-row merge
// window; hurts if partial edge sectors get evicted before merging.

#define D 128
#define THREADS 256
#define WARPS (THREADS / 32)
#define ROWS_PER_WARP 4
#define ROWS_PER_BLOCK (WARPS * ROWS_PER_WARP)   // 32

__global__ void __launch_bounds__(THREADS) projection_kernel(
    const float* __restrict__ x, float* __restrict__ out)
{
    const int warp = threadIdx.x >> 5;
    const int lane = threadIdx.x & 31;
    const long long row0 = (long long)blockIdx.x * ROWS_PER_BLOCK
                         + (long long)warp * ROWS_PER_WARP;

    const float* __restrict__ xr = x + row0 * D + lane;

    // Front-batched, fully coalesced streaming loads: 16 x LDG.32.CS
    float v[ROWS_PER_WARP][4];
    #pragma unroll
    for (int r = 0; r < ROWS_PER_WARP; r++)
        #pragma unroll
        for (int c = 0; c < 4; c++)
            v[r][c] = __ldcs(xr + r * D + c * 32);

    float sq[ROWS_PER_WARP];
    #pragma unroll
    for (int r = 0; r < ROWS_PER_WARP; r++)
        sq[r] = v[r][0] * v[r][0] + v[r][1] * v[r][1]
              + v[r][2] * v[r][2] + v[r][3] * v[r][3];

    // Interleaved warp reductions; afterwards every lane holds all sq[r]
    #pragma unroll
    for (int off = 16; off > 0; off >>= 1)
        #pragma unroll
        for (int r = 0; r < ROWS_PER_WARP; r++)
            sq[r] += __shfl_xor_sync(0xFFFFFFFFu, sq[r], off);

    #pragma unroll
    for (int r = 0; r < ROWS_PER_WARP; r++) {
        const float inv   = 1.0f / (1.0f + sq[r]);
        const float scale = 2.0f * inv;        // = 1 - s

        float* __restrict__ orow = out + (row0 + r) * (D + 1);
        #pragma unroll
        for (int c = 0; c < 4; c++)
            __stcs(orow + lane + c * 32, scale * v[r][c]);
    }

    // Tail scalars: lane r stores s for row (row0 + r) — one STG, 4 active lanes.
    if (lane < ROWS_PER_WARP) {
        const float sql = sq[lane];
        __stcs(out + (row0 + lane) * (D + 1) + D, (sql - 1.0f) / (1.0f + sql));
    }
}

extern "C" void kernel_launch(void* const* d_in, const int* in_sizes, int n_in,
                              void* d_out, int out_size)
{
    const float* x = (const float*)d_in[0];
    float* out = (float*)d_out;
    const int n_rows = in_sizes[0] / D;                    // 1048576
    const int blocks = n_rows / ROWS_PER_BLOCK;            // exact: 32768
    projection_kernel<<<blocks, THREADS>>>(x, out);
}